// round 6
// baseline (speedup 1.0000x reference)
#include <cuda_runtime.h>

// Problem constants
#define BATCH 32
#define SEQ   512
#define DIM   64
#define VOCAB 32000
#define DECAY 0.9f

#define T_CHUNK 32
#define NCHUNK  16                      // SEQ / T_CHUNK
#define DC      0.03433683820292512f    // 0.9^32 (chunk decay)
#define MTERMS  4                       // carry terms kept; err ~0.9^128 = 1.4e-6

// Device-global scratch (statically zero-initialized; flags/done are reset
// by the kernel itself at the end of every launch -> graph-replay safe).
__device__ float g_L[BATCH * NCHUNK * DIM * DIM];   // 8 MB local sums
__device__ int   g_flag[BATCH * NCHUNK];            // L_k published flags
__device__ int   g_done[BATCH];                     // per-batch completion count

// ---------------------------------------------------------------------------
// Fused kernel: gather + local sum (produce L_k) + truncated carry (consume
// L_{k-1..k-4}) + state emission. Grid = 512 blocks (all resident), 256 thr.
// Thread owns a 4x4 tile of the 64x64 matrix.
// ---------------------------------------------------------------------------
__global__ __launch_bounds__(256, 4)
void qmn_fused(const int* __restrict__ x, const float* __restrict__ emb,
               float* __restrict__ out) {
    __shared__ __align__(16) float sc[T_CHUNK * DIM];   // 8 KB

    const int bid = blockIdx.x;
    const int b   = bid >> 4;          // NCHUNK = 16
    const int k   = bid & 15;
    const int tid = threadIdx.x;

    // ---- Gather 32 token embeddings into smem (2 float4 per thread) ----
    #pragma unroll
    for (int h = 0; h < 2; h++) {
        const int q  = tid + h * 256;  // float4 index 0..511
        const int s  = q >> 4;         // token within chunk
        const int d4 = q & 15;
        int tok = x[b * SEQ + k * T_CHUNK + s];
        tok = min(max(tok, 0), VOCAB - 1);
        reinterpret_cast<float4*>(sc)[q] =
            reinterpret_cast<const float4*>(emb + (size_t)tok * DIM)[d4];
    }
    __syncthreads();

    const int i0 = (tid >> 4) * 4;
    const int j0 = (tid & 15) * 4;

    // ---- Produce local decayed sum L_k[i][j] = sum_t 0.9^{T-1-t} c_t[i]c_t[j]
    {
        float4 L[4];
        #pragma unroll
        for (int r = 0; r < 4; r++) L[r] = make_float4(0.f, 0.f, 0.f, 0.f);

        #pragma unroll 4
        for (int t = 0; t < T_CHUNK; t++) {
            const float4 ci = *reinterpret_cast<const float4*>(sc + t * DIM + i0);
            const float4 cj = *reinterpret_cast<const float4*>(sc + t * DIM + j0);
            const float c[4] = {ci.x, ci.y, ci.z, ci.w};
            #pragma unroll
            for (int r = 0; r < 4; r++) {
                L[r].x = fmaf(L[r].x, DECAY, c[r] * cj.x);
                L[r].y = fmaf(L[r].y, DECAY, c[r] * cj.y);
                L[r].z = fmaf(L[r].z, DECAY, c[r] * cj.z);
                L[r].w = fmaf(L[r].w, DECAY, c[r] * cj.w);
            }
        }

        float* Lp = g_L + (size_t)bid * DIM * DIM;
        #pragma unroll
        for (int r = 0; r < 4; r++)
            __stcg(reinterpret_cast<float4*>(Lp + (i0 + r) * DIM + j0), L[r]);
        __threadfence();               // my stores visible at GPU scope
        __syncthreads();               // all threads' stores fenced
        if (tid == 0) atomicExch(&g_flag[bid], 1);   // publish
    }

    // ---- Wait for the carry inputs L_{k-1 .. max(0,k-4)} ----
    const int mlo = (k - MTERMS > 0) ? (k - MTERMS) : 0;
    const int nw  = k - mlo;           // number of flags to wait on (0..4)
    if (tid < nw) {
        volatile int* f = g_flag + b * NCHUNK + (k - 1 - tid);
        while (*f == 0) __nanosleep(128);
    }
    __syncthreads();
    __threadfence();                   // acquire: order L reads after flag obs

    // ---- Truncated carry: acc = sum_m DC^{k-1-m} L_m (+ DC^k I if k<=4) ----
    float4 acc[4];
    #pragma unroll
    for (int r = 0; r < 4; r++) acc[r] = make_float4(0.f, 0.f, 0.f, 0.f);

    const float* Lb = g_L + (size_t)b * NCHUNK * DIM * DIM;
    float w = 1.0f;
    for (int m = k - 1; m >= mlo; m--) {
        const float* Lp = Lb + (size_t)m * DIM * DIM;
        #pragma unroll
        for (int r = 0; r < 4; r++) {
            const float4 l = *reinterpret_cast<const float4*>(Lp + (i0 + r) * DIM + j0);
            acc[r].x = fmaf(w, l.x, acc[r].x);
            acc[r].y = fmaf(w, l.y, acc[r].y);
            acc[r].z = fmaf(w, l.z, acc[r].z);
            acc[r].w = fmaf(w, l.w, acc[r].w);
        }
        w *= DC;
    }
    if (k <= MTERMS) {                 // loop ran k times -> w == DC^k
        #pragma unroll
        for (int r = 0; r < 4; r++) {
            const int i = i0 + r;
            if (i == j0 + 0) acc[r].x += w;
            if (i == j0 + 1) acc[r].y += w;
            if (i == j0 + 2) acc[r].z += w;
            if (i == j0 + 3) acc[r].w += w;
        }
    }

    // ---- Emit 32 states, barrier-free, streaming stores ----
    float* op = out + ((size_t)b * SEQ + (size_t)k * T_CHUNK) * DIM * DIM;

    #pragma unroll 4
    for (int t = 0; t < T_CHUNK; t++) {
        const float4 ci = *reinterpret_cast<const float4*>(sc + t * DIM + i0);
        const float4 cj = *reinterpret_cast<const float4*>(sc + t * DIM + j0);
        const float c[4] = {ci.x, ci.y, ci.z, ci.w};
        #pragma unroll
        for (int r = 0; r < 4; r++) {
            acc[r].x = fmaf(acc[r].x, DECAY, c[r] * cj.x);
            acc[r].y = fmaf(acc[r].y, DECAY, c[r] * cj.y);
            acc[r].z = fmaf(acc[r].z, DECAY, c[r] * cj.z);
            acc[r].w = fmaf(acc[r].w, DECAY, c[r] * cj.w);
        }
        float* ot = op + (size_t)t * DIM * DIM;
        #pragma unroll
        for (int r = 0; r < 4; r++)
            __stcs(reinterpret_cast<float4*>(ot + (i0 + r) * DIM + j0), acc[r]);
    }

    // ---- Reset flags for the next launch (last finisher per batch) ----
    if (tid == 0) {
        const int v = atomicAdd(&g_done[b], 1);
        if (v == NCHUNK - 1) {         // all 16 blocks of batch b finished
            #pragma unroll
            for (int i = 0; i < NCHUNK; i++) g_flag[b * NCHUNK + i] = 0;
            g_done[b] = 0;
        }
    }
}

// ---------------------------------------------------------------------------
// Launch
// ---------------------------------------------------------------------------
extern "C" void kernel_launch(void* const* d_in, const int* in_sizes, int n_in,
                              void* d_out, int out_size) {
    const int*   x   = (const int*)d_in[0];     // [B, S] int32
    const float* emb = (const float*)d_in[1];   // [VOCAB, D] fp32
    float*       out = (float*)d_out;           // [B, S, D, D] fp32

    (void)in_sizes; (void)n_in; (void)out_size;

    qmn_fused<<<BATCH * NCHUNK, 256>>>(x, emb, out);
}